// round 15
// baseline (speedup 1.0000x reference)
#include <cuda_runtime.h>
#include <cuda_bf16.h>
#include <math.h>
#include <stdint.h>

#define BATCH 4
#define SEQ   1024
#define EMB   2048
#define NH    16
#define HD    128
#define MROWS (BATCH*SEQ)   /* 4096 */

// ---------------- scratch (device globals; no allocation allowed) ----------------
__device__ __nv_bfloat16 g_AH[3][(size_t)MROWS*EMB];   // [0]=query [1]=key [2]=value->ctx
__device__ __nv_bfloat16 g_AL[3][(size_t)MROWS*EMB];
__device__ __nv_bfloat16 g_BH[4][(size_t)EMB*EMB];     // Wq Wk Wv Wo
__device__ __nv_bfloat16 g_BL[4][(size_t)EMB*EMB];
__device__ __nv_bfloat16 g_QH[(size_t)MROWS*EMB];
__device__ __nv_bfloat16 g_QL[(size_t)MROWS*EMB];
__device__ __nv_bfloat16 g_KH[(size_t)MROWS*EMB];
__device__ __nv_bfloat16 g_KL[(size_t)MROWS*EMB];
__device__ __nv_bfloat16 g_Vh[(size_t)MROWS*EMB];
__device__ __nv_bfloat16 g_Vl[(size_t)MROWS*EMB];

// ======================= portable PTX helpers (sm_80+) ===========================
__device__ __forceinline__ uint32_t smem_u32(const void* p) {
    uint32_t a;
    asm("{ .reg .u64 t; cvta.to.shared.u64 t, %1; cvt.u32.u64 %0, t; }" : "=r"(a) : "l"(p));
    return a;
}
#define CP_ASYNC16(dst, src) \
    asm volatile("cp.async.cg.shared.global [%0], [%1], 16;" :: "r"(dst), "l"(src) : "memory")
#define CP_COMMIT()   asm volatile("cp.async.commit_group;" ::: "memory")
#define CP_WAIT0()    asm volatile("cp.async.wait_group 0;" ::: "memory")
#define CP_WAIT1()    asm volatile("cp.async.wait_group 1;" ::: "memory")

__device__ __forceinline__ void ldsm_x4(uint32_t& r0, uint32_t& r1, uint32_t& r2,
                                        uint32_t& r3, uint32_t addr) {
    asm volatile("ldmatrix.sync.aligned.m8n8.x4.shared.b16 {%0,%1,%2,%3}, [%4];"
                 : "=r"(r0), "=r"(r1), "=r"(r2), "=r"(r3) : "r"(addr));
}
__device__ __forceinline__ void ldsm_x4_t(uint32_t& r0, uint32_t& r1, uint32_t& r2,
                                          uint32_t& r3, uint32_t addr) {
    asm volatile("ldmatrix.sync.aligned.m8n8.x4.trans.shared.b16 {%0,%1,%2,%3}, [%4];"
                 : "=r"(r0), "=r"(r1), "=r"(r2), "=r"(r3) : "r"(addr));
}
__device__ __forceinline__ void mma16816(float* d, const uint32_t* a, const uint32_t* b) {
    asm volatile("mma.sync.aligned.m16n8k16.row.col.f32.bf16.bf16.f32 "
                 "{%0,%1,%2,%3}, {%4,%5,%6,%7}, {%8,%9}, {%0,%1,%2,%3};"
                 : "+f"(d[0]), "+f"(d[1]), "+f"(d[2]), "+f"(d[3])
                 : "r"(a[0]), "r"(a[1]), "r"(a[2]), "r"(a[3]), "r"(b[0]), "r"(b[1]));
}
__device__ __forceinline__ uint32_t swz64(int row, int colByte) {
    return (uint32_t)(row * 64 + ((((colByte >> 4) ^ (row >> 1)) & 3) * 16));
}
__device__ __forceinline__ uint32_t swz256(int row, int cb) {
    int ch = cb >> 4;
    int sw = (ch & 8) | ((ch ^ row) & 7);
    return (uint32_t)(row * 256 + sw * 16);
}
__device__ __forceinline__ uint32_t packbf(float lo, float hi) {
    __nv_bfloat162 t = __floats2bfloat162_rn(lo, hi);
    return *(uint32_t*)&t;
}
__device__ __forceinline__ float exp2s(float x) {
    x = fmaxf(x, -126.0f);
    int i = __float2int_rn(x);
    float f = x - (float)i;
    float p = 0.00961812911f;
    p = fmaf(p, f, 0.0555041087f);
    p = fmaf(p, f, 0.240226507f);
    p = fmaf(p, f, 0.693147182f);
    p = fmaf(p, f, 1.0f);
    return p * __int_as_float((i + 127) << 23);
}

// ======================= merged split: 7 tensors in one launch ===================
__global__ __launch_bounds__(256)
void split_all(const float* __restrict__ q, const float* __restrict__ k,
               const float* __restrict__ v, const float* __restrict__ wq,
               const float* __restrict__ wk, const float* __restrict__ wv,
               const float* __restrict__ wo,
               __nv_bfloat16* __restrict__ ah, __nv_bfloat16* __restrict__ al,
               __nv_bfloat16* __restrict__ bh, __nv_bfloat16* __restrict__ bl,
               int nX4, int nW4)
{
    int t = blockIdx.y;
    const float* X;
    __nv_bfloat16 *Hi, *Lo;
    int n4;
    const size_t NA = (size_t)MROWS * EMB;
    const size_t NB = (size_t)EMB * EMB;
    if (t < 3) {
        X = (t == 0) ? q : (t == 1) ? k : v;
        Hi = ah + (size_t)t * NA;  Lo = al + (size_t)t * NA;
        n4 = nX4;
    } else {
        int u = t - 3;
        X = (u == 0) ? wq : (u == 1) ? wk : (u == 2) ? wv : wo;
        Hi = bh + (size_t)u * NB;  Lo = bl + (size_t)u * NB;
        n4 = nW4;
    }
    int i = blockIdx.x * 256 + threadIdx.x;
    if (i >= n4) return;
    float4 vv = ((const float4*)X)[i];
    uint32_t h01 = packbf(vv.x, vv.y);
    uint32_t h23 = packbf(vv.z, vv.w);
    float2 f01 = __bfloat1622float2(*(__nv_bfloat162*)&h01);
    float2 f23 = __bfloat1622float2(*(__nv_bfloat162*)&h23);
    uint32_t l01 = packbf(vv.x - f01.x, vv.y - f01.y);
    uint32_t l23 = packbf(vv.z - f23.x, vv.w - f23.y);
    *(uint2*)(Hi + (size_t)i * 4) = make_uint2(h01, h23);
    *(uint2*)(Lo + (size_t)i * 4) = make_uint2(l01, l23);
}

// ======================= split-bf16 GEMM core v2 (R13 proven) ====================
#define GBM 128
#define GBN 128
#define GBK 32
#define OFF_AH 0
#define OFF_AL 8192
#define OFF_BH 16384
#define OFF_BL 24576
#define STAGE_BYTES 32768
#define GEMM_SMEM (3 * STAGE_BYTES)   /* 98304 */

__device__ __forceinline__ void gemm_issue_stage(
    const __nv_bfloat16* __restrict__ Ah, const __nv_bfloat16* __restrict__ Al,
    const __nv_bfloat16* __restrict__ Bh, const __nv_bfloat16* __restrict__ Bl,
    uint32_t sb, int tid, int m0, int n0, int c)
{
    const uint32_t st = sb + (uint32_t)(c % 3) * STAGE_BYTES;
    const int kc = c * GBK;
#pragma unroll
    for (int u = 0; u < 8; ++u) {
        int f = tid + u * 256;
        uint32_t dst; const __nv_bfloat16* gp;
        if (f < 1024) {
            int rel = f & 511;
            int row = rel >> 2, ch = rel & 3;
            const __nv_bfloat16* base = (f < 512) ? Ah : Al;
            gp  = base + (size_t)(m0 + row) * EMB + kc + ch * 8;
            dst = st + ((f < 512) ? OFF_AH : OFF_AL) + swz64(row, ch * 16);
        } else {
            int rel = f & 511;
            int row = rel >> 2, ch = rel & 3;
            const __nv_bfloat16* base = (f < 1536) ? Bh : Bl;
            gp  = base + (size_t)(n0 + row) * EMB + kc + ch * 8;
            dst = st + ((f < 1536) ? OFF_BH : OFF_BL) + swz64(row, ch * 16);
        }
        CP_ASYNC16(dst, gp);
    }
    CP_COMMIT();
}

__device__ __forceinline__ void gemm_core(
    const __nv_bfloat16* __restrict__ Ah, const __nv_bfloat16* __restrict__ Al,
    const __nv_bfloat16* __restrict__ Bh, const __nv_bfloat16* __restrict__ Bl,
    uint32_t sb, int tid, int lane, int wid, int m0, int n0,
    float (&acc)[2][8][4])
{
#pragma unroll
    for (int i = 0; i < 2; ++i)
#pragma unroll
        for (int j = 0; j < 8; ++j)
#pragma unroll
            for (int r = 0; r < 4; ++r) acc[i][j][r] = 0.0f;

    const int warp_m = wid & 3;
    const int warp_n = wid >> 2;
    const int a_row = warp_m * 32 + ((lane >> 3) & 1) * 8 + (lane & 7);
    const int a_cb  = (lane >> 4) * 16;
    const int b_row = warp_n * 64 + ((lane >> 4) & 1) * 8 + (lane & 7);
    const int b_cb  = ((lane >> 3) & 1) * 16;

    gemm_issue_stage(Ah, Al, Bh, Bl, sb, tid, m0, n0, 0);
    gemm_issue_stage(Ah, Al, Bh, Bl, sb, tid, m0, n0, 1);

    const int NC = EMB / GBK;   // 64
    for (int c = 0; c < NC; ++c) {
        CP_WAIT1();
        __syncthreads();
        if (c + 2 < NC) gemm_issue_stage(Ah, Al, Bh, Bl, sb, tid, m0, n0, c + 2);
        else CP_COMMIT();

        const uint32_t st = sb + (uint32_t)(c % 3) * STAGE_BYTES;
#pragma unroll
        for (int ks = 0; ks < 2; ++ks) {
            const int cb = ks * 32;
            uint32_t a[2][2][4];
#pragma unroll
            for (int i = 0; i < 2; ++i) {
                ldsm_x4(a[0][i][0], a[0][i][1], a[0][i][2], a[0][i][3],
                        st + OFF_AH + swz64(a_row + i * 16, a_cb + cb));
                ldsm_x4(a[1][i][0], a[1][i][1], a[1][i][2], a[1][i][3],
                        st + OFF_AL + swz64(a_row + i * 16, a_cb + cb));
            }
            uint32_t b[8][2];
#pragma unroll
            for (int q = 0; q < 4; ++q)
                ldsm_x4(b[2*q][0], b[2*q][1], b[2*q+1][0], b[2*q+1][1],
                        st + OFF_BH + swz64(b_row + q * 16, b_cb + cb));
#pragma unroll
            for (int i = 0; i < 2; ++i)
#pragma unroll
                for (int j = 0; j < 8; ++j) {
                    mma16816(acc[i][j], a[0][i], b[j]);
                    mma16816(acc[i][j], a[1][i], b[j]);
                }
#pragma unroll
            for (int q = 0; q < 4; ++q)
                ldsm_x4(b[2*q][0], b[2*q][1], b[2*q+1][0], b[2*q+1][1],
                        st + OFF_BL + swz64(b_row + q * 16, b_cb + cb));
#pragma unroll
            for (int i = 0; i < 2; ++i)
#pragma unroll
                for (int j = 0; j < 8; ++j)
                    mma16816(acc[i][j], a[0][i], b[j]);
        }
    }
}

// ---- shared epilogue helper: stage acc tile into smem fp32 -------------------
#define SPAD 132
__device__ __forceinline__ void stage_acc(float* stile, int lane, int wid,
                                          const float (&acc)[2][8][4])
{
    const int warp_m = wid & 3, warp_n = wid >> 2;
    const int r0q = lane >> 2, c0q = (lane & 3) * 2;
#pragma unroll
    for (int i = 0; i < 2; ++i) {
#pragma unroll
        for (int j = 0; j < 8; ++j) {
            int lr0 = warp_m * 32 + i * 16 + r0q;
            int lc  = warp_n * 64 + j * 8 + c0q;
            stile[lr0 * SPAD + lc]           = acc[i][j][0];
            stile[lr0 * SPAD + lc + 1]       = acc[i][j][1];
            stile[(lr0 + 8) * SPAD + lc]     = acc[i][j][2];
            stile[(lr0 + 8) * SPAD + lc + 1] = acc[i][j][3];
        }
    }
}

// ---- batched Q/K/V projection GEMM with fused RoPE/V-split epilogues ----------
__global__ __launch_bounds__(256, 2)
void gemm_qkv(const float* __restrict__ cosT, const float* __restrict__ sinT)
{
    extern __shared__ __align__(128) char smc[];
    const uint32_t sb = smem_u32(smc);
    const int tid = threadIdx.x, lane = tid & 31, wid = tid >> 5;
    const int m0 = blockIdx.y * GBM, n0 = blockIdx.x * GBN;
    const int z = blockIdx.z;

    float acc[2][8][4];
    gemm_core(g_AH[z], g_AL[z], g_BH[z], g_BL[z], sb, tid, lane, wid, m0, n0, acc);

    float* stile = (float*)smc;
    __syncthreads();             // all warps done with pipeline smem
    stage_acc(stile, lane, wid, acc);
    __syncthreads();

    const int h = n0 >> 7;       // one head per column block

    if (z == 2) {
        // V: coalesced bf16 split writes [B,H,S,D]
#pragma unroll
        for (int it = 0; it < 16; ++it) {
            int slot = tid + it * 256;        // 4096 = 128 rows x 32 dpairs
            int t  = slot & 31;
            int lr = slot >> 5;
            int d0 = t * 2;
            int gm = m0 + lr;
            int b  = gm >> 10, s = gm & 1023;
            const float* row = stile + lr * SPAD;
            float x1a = row[d0],      x1b = row[d0 + 1];
            float x2a = row[d0 + 64], x2b = row[d0 + 65];
            uint32_t h1 = packbf(x1a, x1b), h2 = packbf(x2a, x2b);
            float2 f1 = __bfloat1622float2(*(__nv_bfloat162*)&h1);
            float2 f2 = __bfloat1622float2(*(__nv_bfloat162*)&h2);
            uint32_t l1 = packbf(x1a - f1.x, x1b - f1.y);
            uint32_t l2 = packbf(x2a - f2.x, x2b - f2.y);
            size_t o = (((size_t)(b * NH + h)) * SEQ + s) * HD + d0;
            *(uint32_t*)(g_Vh + o)      = h1;
            *(uint32_t*)(g_Vl + o)      = l1;
            *(uint32_t*)(g_Vh + o + 64) = h2;
            *(uint32_t*)(g_Vl + o + 64) = l2;
        }
    } else {
        __nv_bfloat16* H = (z == 0) ? g_QH : g_KH;
        __nv_bfloat16* L = (z == 0) ? g_QL : g_KL;
#pragma unroll
        for (int it = 0; it < 16; ++it) {
            int slot = tid + it * 256;
            int t  = slot & 31;
            int lr = slot >> 5;
            int d0 = t * 2;
            int gm = m0 + lr;
            int b  = gm >> 10, s = gm & 1023;
            float2 cc = *(const float2*)(cosT + s * HD + d0);
            float2 ss = *(const float2*)(sinT + s * HD + d0);
            const float* row = stile + lr * SPAD;
            float x1a = row[d0],      x1b = row[d0 + 1];
            float x2a = row[d0 + 64], x2b = row[d0 + 65];
            float r1a = x1a * cc.x - x2a * ss.x, r1b = x1b * cc.y - x2b * ss.y;
            float r2a = x2a * cc.x + x1a * ss.x, r2b = x2b * cc.y + x1b * ss.y;
            uint32_t h1 = packbf(r1a, r1b), h2 = packbf(r2a, r2b);
            float2 f1 = __bfloat1622float2(*(__nv_bfloat162*)&h1);
            float2 f2 = __bfloat1622float2(*(__nv_bfloat162*)&h2);
            uint32_t l1 = packbf(r1a - f1.x, r1b - f1.y);
            uint32_t l2 = packbf(r2a - f2.x, r2b - f2.y);
            size_t o = (((size_t)(b * NH + h)) * SEQ + s) * HD + d0;
            *(uint32_t*)(H + o)      = h1;
            *(uint32_t*)(L + o)      = l1;
            *(uint32_t*)(H + o + 64) = h2;
            *(uint32_t*)(L + o + 64) = l2;
        }
    }
}

// ---- output projection GEMM: coalesced float4 writes via smem stage -----------
__global__ __launch_bounds__(256, 2)
void gemm_out(float* __restrict__ Y)
{
    extern __shared__ __align__(128) char smc[];
    const uint32_t sb = smem_u32(smc);
    const int tid = threadIdx.x, lane = tid & 31, wid = tid >> 5;
    const int m0 = blockIdx.y * GBM, n0 = blockIdx.x * GBN;

    float acc[2][8][4];
    gemm_core(g_AH[2], g_AL[2], g_BH[3], g_BL[3], sb, tid, lane, wid, m0, n0, acc);

    float* stile = (float*)smc;
    __syncthreads();
    stage_acc(stile, lane, wid, acc);
    __syncthreads();

#pragma unroll
    for (int it = 0; it < 16; ++it) {
        int slot = tid + it * 256;        // 4096 = 128 rows x 32 float4
        int t  = slot & 31;
        int lr = slot >> 5;
        const float* row = stile + lr * SPAD + t * 4;
        float4 v = make_float4(row[0], row[1], row[2], row[3]);
        *(float4*)(Y + (size_t)(m0 + lr) * EMB + n0 + t * 4) = v;
    }
}

// =================================================================================
// Tensor-core flash attention v4 (R14 proven): 64-row Q tiles, 128 thr, 2 CTAs/SM.
// =================================================================================
#define A4_QH 0u
#define A4_QL 16384u
#define A4_KV 32768u
#define A4_SMEM 98304

__global__ __launch_bounds__(128, 2)
void attn_tc4()
{
    extern __shared__ __align__(128) char smc[];
    const uint32_t sb = smem_u32(smc);
    const int tid = threadIdx.x, lane = tid & 31, w = tid >> 5;
    const int qt = 15 - blockIdx.x;
    const int bh = blockIdx.y;
    const int q0 = qt * 64;
    const float SC = 0.12751743f;   // log2(e)/sqrt(128)

    {
        const size_t gbase = ((size_t)bh * SEQ + q0) * HD;
#pragma unroll
        for (int u = 0; u < 16; ++u) {
            int f = tid + u * 128;
            int rel = f & 1023;
            int row = rel >> 4, ch = rel & 15;
            const __nv_bfloat16* gp = ((f < 1024) ? g_QH : g_QL)
                                      + gbase + (size_t)row * HD + ch * 8;
            uint32_t dst = sb + ((f < 1024) ? A4_QH : A4_QL) + swz256(row, ch * 16);
            CP_ASYNC16(dst, gp);
        }
        CP_COMMIT();
    }

    auto issue_k = [&](int kt) {
        const size_t gbase = ((size_t)bh * SEQ + kt * 64) * HD;
#pragma unroll
        for (int u = 0; u < 16; ++u) {
            int f = tid + u * 128;
            int rel = f & 1023;
            int row = rel >> 4, ch = rel & 15;
            const __nv_bfloat16* gb = (f < 1024) ? g_KH : g_KL;
            uint32_t dst = sb + A4_KV + ((f < 1024) ? 0u : 16384u) + swz256(row, ch * 16);
            CP_ASYNC16(dst, gb + gbase + (size_t)row * HD + ch * 8);
        }
        CP_COMMIT();
    };
    auto issue_v = [&](int kt) {
        const size_t gbase = ((size_t)bh * SEQ + kt * 64) * HD;
#pragma unroll
        for (int u = 0; u < 16; ++u) {
            int f = tid + u * 128;
            int rel = f & 1023;
            int row = rel >> 4, ch = rel & 15;
            const __nv_bfloat16* gb = (f < 1024) ? g_Vh : g_Vl;
            uint32_t dst = sb + A4_KV + ((f < 1024) ? 32768u : 49152u) + swz256(row, ch * 16);
            CP_ASYNC16(dst, gb + gbase + (size_t)row * HD + ch * 8);
        }
        CP_COMMIT();
    };

    const int nkt = qt + 1;
    issue_k(0);
    issue_v(0);

    const int rA = w * 16 + (lane >> 2);
    const int qa = q0 + rA, qb = qa + 8;
    float O[16][4];
#pragma unroll
    for (int j = 0; j < 16; ++j)
#pragma unroll
        for (int r = 0; r < 4; ++r) O[j][r] = 0.0f;
    float m_a = -1e30f, m_b = -1e30f, l_a = 0.0f, l_b = 0.0f;

    const int qa_row = w * 16 + ((lane >> 3) & 1) * 8 + (lane & 7);
    const int qa_cb  = (lane >> 4) * 16;
    const int kb_row = ((lane >> 4) & 1) * 8 + (lane & 7);
    const int kb_cb  = ((lane >> 3) & 1) * 16;
    const int vt_row = ((lane >> 3) & 1) * 8 + (lane & 7);
    const int vt_cb  = (lane >> 4) * 16;

    for (int kt = 0; kt < nkt; ++kt) {
        CP_WAIT0();
        __syncthreads();
        const uint32_t st = sb + A4_KV;

        float sa[8][4];
#pragma unroll
        for (int j = 0; j < 8; ++j)
#pragma unroll
            for (int r = 0; r < 4; ++r) sa[j][r] = 0.0f;

#pragma unroll
        for (int kk = 0; kk < 8; ++kk) {
            const int cb = kk * 32;
            uint32_t aH[4], aL[4];
            ldsm_x4(aH[0], aH[1], aH[2], aH[3], sb + A4_QH + swz256(qa_row, qa_cb + cb));
            ldsm_x4(aL[0], aL[1], aL[2], aL[3], sb + A4_QL + swz256(qa_row, qa_cb + cb));
#pragma unroll
            for (int g = 0; g < 4; ++g) {
                uint32_t b[4];
                ldsm_x4(b[0], b[1], b[2], b[3],
                        st + swz256(g * 16 + kb_row, kb_cb + cb));
                mma16816(sa[2*g],   aH, b);
                mma16816(sa[2*g+1], aH, b + 2);
                mma16816(sa[2*g],   aL, b);
                mma16816(sa[2*g+1], aL, b + 2);
                ldsm_x4(b[0], b[1], b[2], b[3],
                        st + 16384u + swz256(g * 16 + kb_row, kb_cb + cb));
                mma16816(sa[2*g],   aH, b);
                mma16816(sa[2*g+1], aH, b + 2);
            }
        }

        __syncthreads();
        if (kt + 1 < nkt) issue_k(kt + 1);

        if (kt * 64 + 63 > q0 + w * 16) {
            const int colb = kt * 64 + (lane & 3) * 2;
#pragma unroll
            for (int j = 0; j < 8; ++j) {
                int c0 = colb + j * 8, c1 = c0 + 1;
                if (c0 > qa) sa[j][0] = -1e30f;
                if (c1 > qa) sa[j][1] = -1e30f;
                if (c0 > qb) sa[j][2] = -1e30f;
                if (c1 > qb) sa[j][3] = -1e30f;
            }
        }

        float mxa = sa[0][0], mxb = sa[0][2];
#pragma unroll
        for (int j = 0; j < 8; ++j) {
            mxa = fmaxf(mxa, fmaxf(sa[j][0], sa[j][1]));
            mxb = fmaxf(mxb, fmaxf(sa[j][2], sa[j][3]));
        }
        mxa = fmaxf(mxa, __shfl_xor_sync(0xffffffffu, mxa, 1));
        mxa = fmaxf(mxa, __shfl_xor_sync(0xffffffffu, mxa, 2));
        mxb = fmaxf(mxb, __shfl_xor_sync(0xffffffffu, mxb, 1));
        mxb = fmaxf(mxb, __shfl_xor_sync(0xffffffffu, mxb, 2));
        float mna = fmaxf(m_a, mxa), mnb = fmaxf(m_b, mxb);
        float alpha_a = exp2s((m_a - mna) * SC);
        float alpha_b = exp2s((m_b - mnb) * SC);
        m_a = mna; m_b = mnb;

        float suma = 0.0f, sumb = 0.0f;
#pragma unroll
        for (int j = 0; j < 8; ++j) {
            sa[j][0] = exp2s((sa[j][0] - mna) * SC);
            sa[j][1] = exp2s((sa[j][1] - mna) * SC);
            sa[j][2] = exp2s((sa[j][2] - mnb) * SC);
            sa[j][3] = exp2s((sa[j][3] - mnb) * SC);
            suma += sa[j][0] + sa[j][1];
            sumb += sa[j][2] + sa[j][3];
        }
        suma += __shfl_xor_sync(0xffffffffu, suma, 1);
        suma += __shfl_xor_sync(0xffffffffu, suma, 2);
        sumb += __shfl_xor_sync(0xffffffffu, sumb, 1);
        sumb += __shfl_xor_sync(0xffffffffu, sumb, 2);
        l_a = l_a * alpha_a + suma;
        l_b = l_b * alpha_b + sumb;
#pragma unroll
        for (int j = 0; j < 16; ++j) {
            O[j][0] *= alpha_a; O[j][1] *= alpha_a;
            O[j][2] *= alpha_b; O[j][3] *= alpha_b;
        }

        uint32_t aPh[4][4], aPl[4][4];
#pragma unroll
        for (int k2 = 0; k2 < 4; ++k2) {
            const float* p0 = sa[2*k2];
            const float* p1 = sa[2*k2+1];
            aPh[k2][0] = packbf(p0[0], p0[1]);
            aPh[k2][1] = packbf(p0[2], p0[3]);
            aPh[k2][2] = packbf(p1[0], p1[1]);
            aPh[k2][3] = packbf(p1[2], p1[3]);
            float2 h0 = __bfloat1622float2(*(__nv_bfloat162*)&aPh[k2][0]);
            float2 h1 = __bfloat1622float2(*(__nv_bfloat162*)&aPh[k2][1]);
            float2 h2 = __bfloat1622float2(*(__nv_bfloat162*)&aPh[k2][2]);
            float2 h3 = __bfloat1622float2(*(__nv_bfloat162*)&aPh[k2][3]);
            aPl[k2][0] = packbf(p0[0] - h0.x, p0[1] - h0.y);
            aPl[k2][1] = packbf(p0[2] - h1.x, p0[3] - h1.y);
            aPl[k2][2] = packbf(p1[0] - h2.x, p1[1] - h2.y);
            aPl[k2][3] = packbf(p1[2] - h3.x, p1[3] - h3.y);
        }

#pragma unroll
        for (int g = 0; g < 8; ++g) {
#pragma unroll
            for (int k2 = 0; k2 < 4; ++k2) {
                uint32_t b[4];
                ldsm_x4_t(b[0], b[1], b[2], b[3],
                          st + 32768u + swz256(k2 * 16 + vt_row, g * 32 + vt_cb));
                mma16816(O[2*g],   aPh[k2], b);
                mma16816(O[2*g+1], aPh[k2], b + 2);
                mma16816(O[2*g],   aPl[k2], b);
                mma16816(O[2*g+1], aPl[k2], b + 2);
                ldsm_x4_t(b[0], b[1], b[2], b[3],
                          st + 49152u + swz256(k2 * 16 + vt_row, g * 32 + vt_cb));
                mma16816(O[2*g],   aPh[k2], b);
                mma16816(O[2*g+1], aPh[k2], b + 2);
            }
        }

        __syncthreads();
        if (kt + 1 < nkt) issue_v(kt + 1);
    }

    const int b = bh >> 4, h = bh & 15;
    const float inva = 1.0f / l_a, invb = 1.0f / l_b;
    const size_t base_a = ((size_t)(b * SEQ + qa)) * EMB + h * HD;
    const size_t base_b = ((size_t)(b * SEQ + qb)) * EMB + h * HD;
#pragma unroll
    for (int j = 0; j < 16; ++j) {
        int dcol = j * 8 + (lane & 3) * 2;
        float oa0 = O[j][0] * inva, oa1 = O[j][1] * inva;
        float ob0 = O[j][2] * invb, ob1 = O[j][3] * invb;
        uint32_t ha = packbf(oa0, oa1);
        uint32_t hb = packbf(ob0, ob1);
        float2 fa = __bfloat1622float2(*(__nv_bfloat162*)&ha);
        float2 fb = __bfloat1622float2(*(__nv_bfloat162*)&hb);
        uint32_t la = packbf(oa0 - fa.x, oa1 - fa.y);
        uint32_t lb = packbf(ob0 - fb.x, ob1 - fb.y);
        *(uint32_t*)(g_AH[2] + base_a + dcol) = ha;
        *(uint32_t*)(g_AL[2] + base_a + dcol) = la;
        *(uint32_t*)(g_AH[2] + base_b + dcol) = hb;
        *(uint32_t*)(g_AL[2] + base_b + dcol) = lb;
    }
}

// =================================================================================
extern "C" void kernel_launch(void* const* d_in, const int* in_sizes, int n_in,
                              void* d_out, int out_size)
{
    const float* query = (const float*)d_in[0];
    const float* key   = (const float*)d_in[1];
    const float* value = (const float*)d_in[2];
    const float* cosT  = (const float*)d_in[4];
    const float* sinT  = (const float*)d_in[5];
    const float* Wq    = (const float*)d_in[6];
    const float* Wk    = (const float*)d_in[7];
    const float* Wv    = (const float*)d_in[8];
    const float* Wo    = (const float*)d_in[9];

    __nv_bfloat16 *pAH, *pAL, *pBH, *pBL;
    cudaGetSymbolAddress((void**)&pAH, g_AH);
    cudaGetSymbolAddress((void**)&pAL, g_AL);
    cudaGetSymbolAddress((void**)&pBH, g_BH);
    cudaGetSymbolAddress((void**)&pBL, g_BL);

    cudaFuncSetAttribute(gemm_qkv, cudaFuncAttributeMaxDynamicSharedMemorySize, GEMM_SMEM);
    cudaFuncSetAttribute(gemm_out, cudaFuncAttributeMaxDynamicSharedMemorySize, GEMM_SMEM);
    cudaFuncSetAttribute(attn_tc4, cudaFuncAttributeMaxDynamicSharedMemorySize, A4_SMEM);

    const int nX4 = MROWS * EMB / 4;   // 2097152
    const int nW4 = EMB * EMB / 4;     // 1048576

    // one merged split launch: 3 activations + 4 weights
    split_all<<<dim3(nX4 / 256, 7), 256>>>(
        query, key, value, Wq, Wk, Wv, Wo, pAH, pAL, pBH, pBL, nX4, nW4);

    // Q/K/V projections (128x128 tiles, 2 CTAs/SM) with fused epilogues
    gemm_qkv<<<dim3(EMB / GBN, MROWS / GBM, 3), 256, GEMM_SMEM>>>(cosT, sinT);

    // tensor-core flash attention v4
    attn_tc4<<<dim3(16, 64), 128, A4_SMEM>>>();

    // output projection (coalesced epilogue)
    gemm_out<<<dim3(EMB / GBN, MROWS / GBM), 256, GEMM_SMEM>>>((float*)d_out);
}